// round 12
// baseline (speedup 1.0000x reference)
#include <cuda_runtime.h>
#include <math.h>

// Petrosian fractal features, 5 scales, T=4096, 57 windows/row.
// One WARP per row, 8 rows/CTA, no smem, no __syncthreads.
// Row = 16 chunks of 256 elems (2 x 128-elem prefix segments per chunk).
// Per chunk: 2 LDG.128/lane (2-chunk rotating prefetch), FOUR circular
// shuffles (v0.x, v1.x, d0, e0 from lane+1) and ONE packed redux:
//   contrib = cntLow | cntHigh<<8 | (lane31: tm<<16 | te<<24)
// so segment sums AND both boundary corrections are broadcast in a single
// __reduce_add_sync. Windows: zc([128a,128b)) = S[b] - S[a] - bcorr[b].

#define T_LEN 4096
#define N_WIN 57
#define WARPS 8
#define FULL  0xffffffffu

__global__ __launch_bounds__(256)
void petrosian_kernel(const float* __restrict__ x, float* __restrict__ out, int n_rows) {
    const int lane = threadIdx.x & 31;
    const int wid  = threadIdx.x >> 5;
    const int row  = blockIdx.x * WARPS + wid;
    if (row >= n_rows) return;

    const float4* p4 = (const float4*)(x + (size_t)row * T_LEN);

    // 2-chunk rotating prefetch (4 LDG.128 in flight)
    float4 b0[2], b1[2];
    #pragma unroll
    for (int i = 0; i < 2; i++) {
        b0[i] = p4[64 * i + lane];
        b1[i] = p4[64 * i + 32 + lane];
    }

    int   segreg = 0, bcreg = 0;   // lane m: segment-m sum / bcorr[m+1]
    int   prevHigh = 0;
    float cx = 0.0f, cd = 0.0f;    // lane 31 carries: x[255], d[254] of prev chunk
    const int nl = (lane + 1) & 31;

    #pragma unroll
    for (int c = 0; c < 16; c++) {
        float4 v0 = b0[c & 1], v1 = b1[c & 1];
        if (c < 14) {
            b0[c & 1] = p4[64 * (c + 2) + lane];
            b1[c & 1] = p4[64 * (c + 2) + 32 + lane];
        }

        // local diffs
        float d0 = v0.y - v0.x, d1 = v0.z - v0.y, d2 = v0.w - v0.z;
        float e0 = v1.y - v1.x, e1 = v1.z - v1.y, e2 = v1.w - v1.z;

        // 4 circular shuffles
        float h0x = __shfl_sync(FULL, v0.x, nl);  // next lane's x (low half)
        float h1x = __shfl_sync(FULL, v1.x, nl);  // next lane's x (high half)
        float dd4 = __shfl_sync(FULL, d0,  nl);   // next lane's first low diff
        float ee4 = __shfl_sync(FULL, e0,  nl);   // next lane's first high diff

        // low half: j = 256c + 4l + {0..3}
        //   lanes<31: d3 = h0x - v0.w, d4 = dd4
        //   lane 31:  d3 = h1x - v0.w (x[+128]), d4 = ee4 (d[+128])
        float d3 = ((lane < 31) ? h0x : h1x) - v0.w;
        float d4 = (lane < 31) ? dd4 : ee4;
        int sl2 = (d2 * d3 < 0.0f) ? 1 : 0;      // s[...+126] at lane31
        int sl3 = (d3 * d4 < 0.0f) ? 1 : 0;      // s[...+127] at lane31
        int cntLow = ((d0 * d1 < 0.0f) ? 1 : 0) + ((d1 * d2 < 0.0f) ? 1 : 0) + sl2 + sl3;

        // high half: j = 256c + 128 + 4l + {0..3}; lane31's last 2 deferred
        float e3 = h1x - v1.w, e4 = ee4;
        int cntHigh = ((e0 * e1 < 0.0f) ? 1 : 0) + ((e1 * e2 < 0.0f) ? 1 : 0);
        if (lane < 31)
            cntHigh += ((e2 * e3 < 0.0f) ? 1 : 0) + ((e3 * e4 < 0.0f) ? 1 : 0);

        // lane 31 extras: tm = bcorr[2c+1]; te = bcorr[2c] (prev-chunk boundary)
        int contrib = cntLow | (cntHigh << 8);
        if (lane == 31) {
            int te = 0;
            if (c > 0) {
                float dA = h0x - cx;   // d[256c-1]  (h0x@31 = lane0's v0.x = x[256c])
                float dB = dd4;        // d[256c]    (dd4@31 = lane0's d0)
                te = ((cd * dA < 0.0f) ? 1 : 0) + ((dA * dB < 0.0f) ? 1 : 0);
            }
            contrib |= ((sl2 + sl3) << 16) | (te << 24);
        }

        int total = __reduce_add_sync(FULL, contrib);
        int lowS = total & 255, highS = (total >> 8) & 255;
        int tm_b = (total >> 16) & 255, te_b = total >> 24;

        if (c > 0 && lane == 2 * c - 1) { segreg = prevHigh + te_b; bcreg = te_b; }
        if (lane == 2 * c)              { segreg = lowS;            bcreg = tm_b; }
        prevHigh = highS;

        cx = v1.w;   // x[256c+255] (local to lane 31)
        cd = e2;     // d[256c+254]
    }
    // final high segment (m=31): s[4094], s[4095] invalid -> te = 0
    if (lane == 31) { segreg = prevHigh; bcreg = 0; }

    // inclusive scan: sc at lane l = S[l+1]
    int sc = segreg;
    #pragma unroll
    for (int off = 1; off < 32; off <<= 1) {
        int n = __shfl_up_sync(FULL, sc, off);
        if (lane >= off) sc += n;
    }

    // 57 outputs, 2 per lane
    const size_t obase = (size_t)row * N_WIN;
    #pragma unroll
    for (int half = 0; half < 2; half++) {
        int k  = lane + half * 32;
        int kk = (k < N_WIN) ? k : 0;
        int w, a; float L;
        if      (kk < 1)  { w = 4096; a = 0;             L = 3.612359948f; }
        else if (kk < 4)  { w = 2048; a = (kk - 1) * 8;  L = 3.311329954f; }
        else if (kk < 11) { w = 1024; a = (kk - 4) * 4;  L = 3.010299957f; }
        else if (kk < 26) { w = 512;  a = (kk - 11) * 2; L = 2.709269961f; }
        else              { w = 256;  a = kk - 26;       L = 2.408239965f; }
        int b = a + (w >> 7);

        int Sb = __shfl_sync(FULL, sc, b - 1);
        int Sa = __shfl_sync(FULL, sc, (a > 0) ? (a - 1) : 0);
        if (a == 0) Sa = 0;
        int bc = __shfl_sync(FULL, bcreg, b - 1);

        if (k < N_WIN) {
            float zc = (float)(Sb - Sa - bc);
            float wf = (float)w;
            float denom = L + log10f(wf / (wf + 0.4f * zc));
            out[obase + k] = L / denom;
        }
    }
}

extern "C" void kernel_launch(void* const* d_in, const int* in_sizes, int n_in,
                              void* d_out, int out_size) {
    const float* x = (const float*)d_in[0];
    float* out = (float*)d_out;
    int n_rows = in_sizes[0] / T_LEN;               // B*C = 4096
    int n_blocks = (n_rows + WARPS - 1) / WARPS;    // 512
    petrosian_kernel<<<n_blocks, 256>>>(x, out, n_rows);
}

// round 13
// speedup vs baseline: 1.4837x; 1.4837x over previous
#include <cuda_runtime.h>
#include <math.h>

// Petrosian fractal features, 5 scales, T=4096, 57 windows/row.
// TWO warps per row (each owns 2048 elems = 8 chunks of 256); 8 warps/CTA =
// 4 rows/CTA; grid 1024 (occ ~60%). 3-deep rotating chunk prefetch => 6
// LDG.128 (384B) in flight per lane; occ x MLP ~= 15KB/SM ~ BDP.
// Per chunk: halo via circular shfl, packed dual-segment __reduce_add_sync.
// Halves join via ~1KB smem + one __syncthreads; the 2 indicators straddling
// elem 2048 are fixed up by the first-half warp with one uniform float2 load.
// Windows: zc([128a,128b)) = S[b] - S[a] - bcorr[b].

#define T_LEN 4096
#define N_WIN 57
#define ROWS_PER_CTA 4
#define PF    3
#define FULL  0xffffffffu

__global__ __launch_bounds__(256, 5)
void petrosian_kernel(const float* __restrict__ x, float* __restrict__ out) {
    __shared__ int segsm[ROWS_PER_CTA][32];
    __shared__ int bcsm[ROWS_PER_CTA][33];

    const int lane = threadIdx.x & 31;
    const int wid  = threadIdx.x >> 5;
    const int r    = wid >> 1;          // CTA-local row 0..3
    const int h    = wid & 1;           // half 0 / 1
    const int row  = blockIdx.x * ROWS_PER_CTA + r;

    const float* rowp = x + (size_t)row * T_LEN;
    const float4* p4  = (const float4*)(rowp + h * 2048);

    // 3-chunk rotating prefetch (6 LDG.128 in flight)
    float4 b0[PF], b1[PF];
    #pragma unroll
    for (int i = 0; i < PF; i++) {
        b0[i] = p4[64 * i + lane];
        b1[i] = p4[64 * i + 32 + lane];
    }

    int   segreg = 0, bcreg = 0;     // local lane m (<16): seg sum m / bcorr[m+1]
    int   prevHigh = 0;
    float cx = 0.0f, cd = 0.0f;      // lane 31 carries: x[255], d[254] of prev chunk
    const int nl = (lane + 1) & 31;

    #pragma unroll
    for (int c = 0; c < 8; c++) {
        float4 v0 = b0[c % PF], v1 = b1[c % PF];
        if (c < 8 - PF) {
            b0[c % PF] = p4[64 * (c + PF) + lane];
            b1[c % PF] = p4[64 * (c + PF) + 32 + lane];
        }

        float h0x = __shfl_sync(FULL, v0.x, nl);
        float h0y = __shfl_sync(FULL, v0.y, nl);
        float h1x = __shfl_sync(FULL, v1.x, nl);
        float h1y = __shfl_sync(FULL, v1.y, nl);

        // deferred boundary of previous chunk: s[256c-2], s[256c-1] (local)
        if (c > 0) {
            float dA = h0x - cx;       // d[256c-1]
            float dB = h0y - h0x;      // d[256c]
            int te = ((cd * dA < 0.0f) ? 1 : 0) + ((dA * dB < 0.0f) ? 1 : 0);
            te = __shfl_sync(FULL, te, 31);
            if (lane == 2 * c - 1) { segreg = prevHigh + te; bcreg = te; }
        }

        // low half: j = 256c + 4l + {0..3}; lane31 halo = lane0's v1
        float fhx = (lane < 31) ? h0x : h1x;
        float fhy = (lane < 31) ? h0y : h1y;
        float d0 = v0.y - v0.x, d1 = v0.z - v0.y, d2 = v0.w - v0.z;
        float d3 = fhx - v0.w,  d4 = fhy - fhx;
        int sl2 = (d2 * d3 < 0.0f) ? 1 : 0;
        int sl3 = (d3 * d4 < 0.0f) ? 1 : 0;
        int cntLow = ((d0 * d1 < 0.0f) ? 1 : 0) + ((d1 * d2 < 0.0f) ? 1 : 0) + sl2 + sl3;
        int tm = __shfl_sync(FULL, sl2 + sl3, 31);

        // high half: j = 256c + 128 + 4l + {0..3}; lane31: last 2 deferred
        float e0 = v1.y - v1.x, e1 = v1.z - v1.y, e2 = v1.w - v1.z;
        float e3 = h1x - v1.w,  e4 = h1y - h1x;
        int cntHigh = ((e0 * e1 < 0.0f) ? 1 : 0) + ((e1 * e2 < 0.0f) ? 1 : 0);
        if (lane < 31)
            cntHigh += ((e2 * e3 < 0.0f) ? 1 : 0) + ((e3 * e4 < 0.0f) ? 1 : 0);

        int total = __reduce_add_sync(FULL, cntLow | (cntHigh << 16));
        if (lane == 2 * c) { segreg = total & 0xFFFF; bcreg = tm; }
        prevHigh = total >> 16;

        cx = v1.w;   // x[256c+255] (local)
        cd = e2;     // d[256c+254] (local)
    }

    // final local segment (m = 15)
    if (h == 0) {
        // straddling indicators s[2046], s[2047] need x[2048], x[2049]
        float2 nx = *(const float2*)(rowp + 2048);   // uniform address
        float cx31 = __shfl_sync(FULL, cx, 31);
        float cd31 = __shfl_sync(FULL, cd, 31);
        float dA = nx.x - cx31;     // d[2047]
        float dB = nx.y - nx.x;     // d[2048]
        int te = ((cd31 * dA < 0.0f) ? 1 : 0) + ((dA * dB < 0.0f) ? 1 : 0);
        if (lane == 15) { segreg = prevHigh + te; bcreg = te; }
    } else {
        // global end: s[4094], s[4095] invalid
        if (lane == 15) { segreg = prevHigh; bcreg = 0; }
    }

    // publish 16 segment sums + bcorr entries
    if (lane < 16) {
        segsm[r][h * 16 + lane] = segreg;
        bcsm[r][h * 16 + lane + 1] = bcreg;
    }
    __syncthreads();

    // ---- warp w < 4: scan row w's 32 segments, emit 57 outputs ----
    if (wid < ROWS_PER_CTA) {
        const int rr = wid;
        int sc = segsm[rr][lane];
        #pragma unroll
        for (int off = 1; off < 32; off <<= 1) {
            int n = __shfl_up_sync(FULL, sc, off);
            if (lane >= off) sc += n;          // sc = S[lane+1]
        }

        const size_t obase = (size_t)(blockIdx.x * ROWS_PER_CTA + rr) * N_WIN;
        #pragma unroll
        for (int half = 0; half < 2; half++) {
            int k  = lane + half * 32;
            int kk = (k < N_WIN) ? k : 0;
            int w, a; float L;
            if      (kk < 1)  { w = 4096; a = 0;             L = 3.612359948f; }
            else if (kk < 4)  { w = 2048; a = (kk - 1) * 8;  L = 3.311329954f; }
            else if (kk < 11) { w = 1024; a = (kk - 4) * 4;  L = 3.010299957f; }
            else if (kk < 26) { w = 512;  a = (kk - 11) * 2; L = 2.709269961f; }
            else              { w = 256;  a = kk - 26;       L = 2.408239965f; }
            int b = a + (w >> 7);

            int Sb = __shfl_sync(FULL, sc, b - 1);
            int Sa = __shfl_sync(FULL, sc, (a > 0) ? (a - 1) : 0);
            if (a == 0) Sa = 0;

            if (k < N_WIN) {
                float zc = (float)(Sb - Sa - bcsm[rr][b]);
                float wf = (float)w;
                float denom = L + log10f(wf / (wf + 0.4f * zc));
                out[obase + k] = L / denom;
            }
        }
    }
}

extern "C" void kernel_launch(void* const* d_in, const int* in_sizes, int n_in,
                              void* d_out, int out_size) {
    const float* x = (const float*)d_in[0];
    float* out = (float*)d_out;
    int n_rows = in_sizes[0] / T_LEN;                    // 4096
    int n_blocks = n_rows / ROWS_PER_CTA;                // 1024
    petrosian_kernel<<<n_blocks, 256>>>(x, out);
}